// round 1
// baseline (speedup 1.0000x reference)
#include <cuda_runtime.h>
#include <cuda_bf16.h>

#define NN 131072
#define EE 2097152
#define CIN 64
#define HID 64

// ---------------- device scratch (static; no allocation allowed) ----------------
__device__ float g_dis[NN];            // degree accumulator, then rsqrt(deg)
__device__ float g_norm[EE];           // per-edge symmetric norm
__device__ float g_aggx[NN * 64];      // A_norm @ x
__device__ float g_h1[NN * 128];       // relu(aggx @ W1 + b1)
__device__ float g_h2t[NN * 64];       // h1 @ W2
__device__ float g_h2[NN * 64];        // A_norm @ h2t   (bias+relu fused into FC)

__device__ __forceinline__ void red_add_f32x4(float* addr, float4 v) {
    asm volatile("red.global.add.v4.f32 [%0], {%1,%2,%3,%4};"
                 :: "l"(addr), "f"(v.x), "f"(v.y), "f"(v.z), "f"(v.w) : "memory");
}

// ---------------- normalization ----------------
__global__ void k_deg_init() {
    int i = blockIdx.x * blockDim.x + threadIdx.x;
    if (i < NN) g_dis[i] = 1.0f;   // self-loop weight
}

__global__ void k_deg_acc(const int* __restrict__ ei, const float* __restrict__ ew) {
    int e = blockIdx.x * blockDim.x + threadIdx.x;
    if (e < EE) atomicAdd(&g_dis[ei[EE + e]], ew[e]);
}

__global__ void k_dis() {
    int i = blockIdx.x * blockDim.x + threadIdx.x;
    if (i < NN) g_dis[i] = rsqrtf(g_dis[i]);   // deg >= 1 always
}

__global__ void k_norm(const int* __restrict__ ei, const float* __restrict__ ew) {
    int e = blockIdx.x * blockDim.x + threadIdx.x;
    if (e < EE) {
        int s = ei[e], d = ei[EE + e];
        g_norm[e] = g_dis[s] * ew[e] * g_dis[d];
    }
}

// ---------------- aggregation (C = 64 features) ----------------
// Out[i] = X[i] * dis[i]^2  (self-loop contribution, also initializes Out)
__global__ void k_self_init(const float* __restrict__ X, float* __restrict__ Out) {
    int t = blockIdx.x * blockDim.x + threadIdx.x;   // N*16 threads
    if (t >= NN * 16) return;
    int row = t >> 4;
    float sn = g_dis[row];
    sn = sn * sn;
    float4 v = ((const float4*)X)[t];
    v.x *= sn; v.y *= sn; v.z *= sn; v.w *= sn;
    ((float4*)Out)[t] = v;
}

// Out[d] += norm[e] * X[s]   via vector reductions (16 threads per edge)
__global__ void k_agg(const float* __restrict__ X, float* __restrict__ Out,
                      const int* __restrict__ ei) {
    int t = blockIdx.x * blockDim.x + threadIdx.x;   // E*16 threads
    if (t >= EE * 16) return;
    int e = t >> 4;
    int p = t & 15;
    int s = ei[e];
    int d = ei[EE + e];
    float nrm = g_norm[e];
    float4 v = ((const float4*)X)[s * 16 + p];
    v.x *= nrm; v.y *= nrm; v.z *= nrm; v.w *= nrm;
    red_add_f32x4(Out + d * 64 + p * 4, v);
}

// ---------------- GEMM: Y[N,NC] = X[N,K] @ W[K,NC] (+bias, relu) ----------------
// Tile: RT rows x NC cols per block. Each thread: 8 rows x 4 cols.
// X tile transposed in shared (stride RT+4 -> conflict-light, float4-aligned).
// W streamed through L1 (32 KB, fully resident).
template<int K, int NC, int RT, bool BIAS_RELU>
__global__ void gemm_k(const float* __restrict__ X, const float* __restrict__ W,
                       const float* __restrict__ bias, float* __restrict__ Y) {
    constexpr int THREADS = (RT / 8) * (NC / 4);
    constexpr int XS = RT + 4;
    __shared__ float sX[K * XS];

    int tid = threadIdx.x;
    int row0 = blockIdx.x * RT;

    // load X tile transposed: sX[k][r]
    #pragma unroll 4
    for (int idx = tid; idx < RT * K; idx += THREADS) {
        int r = idx / K;
        int k = idx - r * K;
        sX[k * XS + r] = X[(row0 + r) * K + k];
    }
    __syncthreads();

    int cg = tid % (NC / 4);
    int rg = tid / (NC / 4);
    int c0 = cg * 4;
    int r0 = rg * 8;

    float acc[8][4];
    #pragma unroll
    for (int r = 0; r < 8; r++)
        #pragma unroll
        for (int c = 0; c < 4; c++) acc[r][c] = 0.0f;

    #pragma unroll 8
    for (int k = 0; k < K; k++) {
        float4 b4 = __ldg((const float4*)(W + k * NC + c0));
        float4 a0 = *(const float4*)&sX[k * XS + r0];
        float4 a1 = *(const float4*)&sX[k * XS + r0 + 4];
        float a[8] = {a0.x, a0.y, a0.z, a0.w, a1.x, a1.y, a1.z, a1.w};
        #pragma unroll
        for (int r = 0; r < 8; r++) {
            acc[r][0] = fmaf(a[r], b4.x, acc[r][0]);
            acc[r][1] = fmaf(a[r], b4.y, acc[r][1]);
            acc[r][2] = fmaf(a[r], b4.z, acc[r][2]);
            acc[r][3] = fmaf(a[r], b4.w, acc[r][3]);
        }
    }

    float4 bb = make_float4(0.f, 0.f, 0.f, 0.f);
    if (BIAS_RELU) bb = *(const float4*)&bias[c0];
    #pragma unroll
    for (int r = 0; r < 8; r++) {
        float4 o;
        o.x = acc[r][0] + bb.x;
        o.y = acc[r][1] + bb.y;
        o.z = acc[r][2] + bb.z;
        o.w = acc[r][3] + bb.w;
        if (BIAS_RELU) {
            o.x = fmaxf(o.x, 0.f); o.y = fmaxf(o.y, 0.f);
            o.z = fmaxf(o.z, 0.f); o.w = fmaxf(o.w, 0.f);
        }
        *(float4*)&Y[(row0 + r0 + r) * NC + c0] = o;
    }
}

// ---------------- FC + softmax (fuses layer-2 bias + relu) ----------------
// logits[g][c] = sum_j relu(h2[g*8192+j] + b2[j%64]) * Wfc[j][c] + bfc[c]
__global__ void fc_softmax(const float* __restrict__ H, const float* __restrict__ Wfc,
                           const float* __restrict__ bfc, const float* __restrict__ b2,
                           float* __restrict__ out) {
    int g = blockIdx.x;
    int tid = threadIdx.x;      // 256
    const float* hrow = H + g * 8192;

    float a0 = 0.f, a1 = 0.f, a2 = 0.f, a3 = 0.f;
    for (int j = tid; j < 8192; j += 256) {
        float v = hrow[j] + b2[j & 63];
        v = fmaxf(v, 0.f);
        float4 w = __ldg((const float4*)Wfc + j);
        a0 = fmaf(v, w.x, a0);
        a1 = fmaf(v, w.y, a1);
        a2 = fmaf(v, w.z, a2);
        a3 = fmaf(v, w.w, a3);
    }
    // warp reduce
    #pragma unroll
    for (int off = 16; off > 0; off >>= 1) {
        a0 += __shfl_xor_sync(0xffffffffu, a0, off);
        a1 += __shfl_xor_sync(0xffffffffu, a1, off);
        a2 += __shfl_xor_sync(0xffffffffu, a2, off);
        a3 += __shfl_xor_sync(0xffffffffu, a3, off);
    }
    __shared__ float sred[8][4];
    int lane = tid & 31, warp = tid >> 5;
    if (lane == 0) {
        sred[warp][0] = a0; sred[warp][1] = a1;
        sred[warp][2] = a2; sred[warp][3] = a3;
    }
    __syncthreads();
    if (tid == 0) {
        float l[4];
        #pragma unroll
        for (int c = 0; c < 4; c++) {
            float s = bfc[c];
            #pragma unroll
            for (int w = 0; w < 8; w++) s += sred[w][c];
            l[c] = s;
        }
        float m = fmaxf(fmaxf(l[0], l[1]), fmaxf(l[2], l[3]));
        float e0 = __expf(l[0] - m), e1 = __expf(l[1] - m);
        float e2 = __expf(l[2] - m), e3 = __expf(l[3] - m);
        float inv = 1.0f / (e0 + e1 + e2 + e3);
        out[g * 4 + 0] = e0 * inv;
        out[g * 4 + 1] = e1 * inv;
        out[g * 4 + 2] = e2 * inv;
        out[g * 4 + 3] = e3 * inv;
    }
}

// ---------------- launch ----------------
extern "C" void kernel_launch(void* const* d_in, const int* in_sizes, int n_in,
                              void* d_out, int out_size) {
    const float* x   = (const float*)d_in[0];
    const int*   ei  = (const int*)d_in[1];
    const float* ew  = (const float*)d_in[2];
    const float* W1  = (const float*)d_in[3];
    const float* b1  = (const float*)d_in[4];
    const float* W2  = (const float*)d_in[5];
    const float* b2  = (const float*)d_in[6];
    const float* Wfc = (const float*)d_in[7];
    const float* bfc = (const float*)d_in[8];
    float* out = (float*)d_out;

    float* aggx; cudaGetSymbolAddress((void**)&aggx, g_aggx);
    float* h1;   cudaGetSymbolAddress((void**)&h1, g_h1);
    float* h2t;  cudaGetSymbolAddress((void**)&h2t, g_h2t);
    float* h2;   cudaGetSymbolAddress((void**)&h2, g_h2);

    // normalization
    k_deg_init<<<NN / 256, 256>>>();
    k_deg_acc<<<EE / 256, 256>>>(ei, ew);
    k_dis<<<NN / 256, 256>>>();
    k_norm<<<EE / 256, 256>>>(ei, ew);

    // layer 1: aggregate x (64 feats), then GEMM (64->128) with bias+relu
    k_self_init<<<NN * 16 / 256, 256>>>(x, aggx);
    k_agg<<<EE * 16 / 256, 256>>>(x, aggx, ei);
    gemm_k<64, 128, 64, true><<<NN / 64, 256>>>(aggx, W1, b1, h1);

    // layer 2: GEMM (128->64), then aggregate; bias+relu deferred to FC
    gemm_k<128, 64, 64, false><<<NN / 64, 128>>>(h1, W2, nullptr, h2t);
    k_self_init<<<NN * 16 / 256, 256>>>(h2t, h2);
    k_agg<<<EE * 16 / 256, 256>>>(h2t, h2, ei);

    // FC + softmax
    fc_softmax<<<1024, 256>>>(h2, Wfc, bfc, b2, out);
}

// round 3
// speedup vs baseline: 1.3168x; 1.3168x over previous
#include <cuda_runtime.h>
#include <cuda_bf16.h>

#define NN 131072
#define EE 2097152

// ---------------- device scratch (static; no allocation allowed) ----------------
__device__ float g_dis[NN];            // degree accumulator -> rsqrt(deg)
__device__ int   g_cnt[NN];            // in-degree histogram (preserved)
__device__ int   g_rowptr[NN];         // exclusive scan of g_cnt
__device__ int   g_cur[NN];            // scatter cursor (copy of rowptr)
__device__ int   g_blksum[128];        // scan block totals
__device__ int   g_blkoff[128];        // scanned block offsets
__device__ int2  g_csr[EE];            // (src, __float_as_int(norm)) per edge, grouped by dst
__device__ float g_aggx[NN * 64];      // A_norm @ x
__device__ float g_h1[NN * 128];       // relu(aggx @ W1 + b1)
__device__ float g_h2t[NN * 64];       // h1 @ W2
__device__ float g_h2[NN * 64];        // A_norm @ h2t (bias+relu fused into FC)

// ---------------- degree + histogram ----------------
__global__ void k_init() {
    int i = blockIdx.x * blockDim.x + threadIdx.x;
    if (i < NN) { g_dis[i] = 1.0f; g_cnt[i] = 0; }   // self-loop weight = 1
}

__global__ void k_deg_hist(const int* __restrict__ ei, const float* __restrict__ ew) {
    int e = blockIdx.x * blockDim.x + threadIdx.x;
    if (e < EE) {
        int d = ei[EE + e];
        atomicAdd(&g_dis[d], ew[e]);
        atomicAdd(&g_cnt[d], 1);
    }
}

__global__ void k_dis() {
    int i = blockIdx.x * blockDim.x + threadIdx.x;
    if (i < NN) g_dis[i] = rsqrtf(g_dis[i]);   // deg >= 1 always (self-loop)
}

// ---------------- exclusive scan of g_cnt (131072 = 128 blocks x 1024 elems) ----------------
__global__ void k_scan1() {
    __shared__ int warp_s[8];
    int b = blockIdx.x, t = threadIdx.x;
    int base = b * 1024 + t * 4;
    int4 c = *(const int4*)&g_cnt[base];
    int s0 = c.x, s1 = s0 + c.y, s2 = s1 + c.z, s3 = s2 + c.w;
    int tsum = s3;
    int lane = t & 31, warp = t >> 5;
    int v = tsum;
    #pragma unroll
    for (int off = 1; off < 32; off <<= 1) {
        int u = __shfl_up_sync(0xffffffffu, v, off);
        if (lane >= off) v += u;
    }
    if (lane == 31) warp_s[warp] = v;
    __syncthreads();
    if (t < 8) {
        int x = warp_s[t];
        #pragma unroll
        for (int off = 1; off < 8; off <<= 1) {
            int u = __shfl_up_sync(0xffu, x, off);
            if (t >= off) x += u;
        }
        warp_s[t] = x;
    }
    __syncthreads();
    int woff = (warp > 0) ? warp_s[warp - 1] : 0;
    int texcl = woff + v - tsum;
    g_rowptr[base + 0] = texcl;
    g_rowptr[base + 1] = texcl + s0;
    g_rowptr[base + 2] = texcl + s1;
    g_rowptr[base + 3] = texcl + s2;
    if (t == 255) g_blksum[b] = woff + v;
}

__global__ void k_scan2() {
    __shared__ int sh[128];
    int t = threadIdx.x;
    int v = g_blksum[t];
    sh[t] = v;
    __syncthreads();
    for (int off = 1; off < 128; off <<= 1) {
        int u = (t >= off) ? sh[t - off] : 0;
        __syncthreads();
        sh[t] += u;
        __syncthreads();
    }
    g_blkoff[t] = sh[t] - v;   // exclusive
}

__global__ void k_scan3() {
    int i = blockIdx.x * blockDim.x + threadIdx.x;
    if (i < NN) {
        int r = g_rowptr[i] + g_blkoff[i >> 10];
        g_rowptr[i] = r;
        g_cur[i] = r;
    }
}

// ---------------- scatter edges into CSR, norm computed inline ----------------
__global__ void k_scatter(const int* __restrict__ ei, const float* __restrict__ ew) {
    int e = blockIdx.x * blockDim.x + threadIdx.x;
    if (e >= EE) return;
    int s = ei[e], d = ei[EE + e];
    float nrm = g_dis[s] * ew[e] * g_dis[d];
    int pos = atomicAdd(&g_cur[d], 1);
    g_csr[pos] = make_int2(s, __float_as_int(nrm));
}

// ---------------- CSR gather aggregation: one warp per node, 64 feats ----------------
// Out[n] = dis[n]^2 * X[n] + sum_{e in in(n)} norm[e] * X[src[e]]
__global__ void k_agg_csr(const float* __restrict__ X, float* __restrict__ Out) {
    int warp = threadIdx.x >> 5;
    int lane = threadIdx.x & 31;
    int node = blockIdx.x * 8 + warp;
    const float2* X2 = (const float2*)X;

    float sn = g_dis[node];
    sn = sn * sn;
    float2 xs = X2[node * 32 + lane];
    float2 acc = make_float2(sn * xs.x, sn * xs.y);

    int beg = g_rowptr[node];
    int end = beg + g_cnt[node];
    #pragma unroll 4
    for (int j = beg; j < end; j++) {
        int2 pr = g_csr[j];                       // uniform -> broadcast
        float nrm = __int_as_float(pr.y);
        float2 v = X2[pr.x * 32 + lane];          // coalesced 256B gather
        acc.x = fmaf(nrm, v.x, acc.x);
        acc.y = fmaf(nrm, v.y, acc.y);
    }
    ((float2*)Out)[node * 32 + lane] = acc;
}

// ---------------- GEMM: Y[N,NC] = X[N,K] @ W[K,NC] (+bias, relu) ----------------
template<int K, int NC, int RT, bool BIAS_RELU>
__global__ void gemm_k(const float* __restrict__ X, const float* __restrict__ W,
                       const float* __restrict__ bias, float* __restrict__ Y) {
    constexpr int THREADS = (RT / 8) * (NC / 4);
    constexpr int XS = RT + 4;
    __shared__ float sX[K * XS];

    int tid = threadIdx.x;
    int row0 = blockIdx.x * RT;

    #pragma unroll 4
    for (int idx = tid; idx < RT * K; idx += THREADS) {
        int r = idx / K;
        int k = idx - r * K;
        sX[k * XS + r] = X[(row0 + r) * K + k];
    }
    __syncthreads();

    int cg = tid % (NC / 4);
    int rg = tid / (NC / 4);
    int c0 = cg * 4;
    int r0 = rg * 8;

    float acc[8][4];
    #pragma unroll
    for (int r = 0; r < 8; r++)
        #pragma unroll
        for (int c = 0; c < 4; c++) acc[r][c] = 0.0f;

    #pragma unroll 8
    for (int k = 0; k < K; k++) {
        float4 b4 = __ldg((const float4*)(W + k * NC + c0));
        float4 a0 = *(const float4*)&sX[k * XS + r0];
        float4 a1 = *(const float4*)&sX[k * XS + r0 + 4];
        float a[8] = {a0.x, a0.y, a0.z, a0.w, a1.x, a1.y, a1.z, a1.w};
        #pragma unroll
        for (int r = 0; r < 8; r++) {
            acc[r][0] = fmaf(a[r], b4.x, acc[r][0]);
            acc[r][1] = fmaf(a[r], b4.y, acc[r][1]);
            acc[r][2] = fmaf(a[r], b4.z, acc[r][2]);
            acc[r][3] = fmaf(a[r], b4.w, acc[r][3]);
        }
    }

    float4 bb = make_float4(0.f, 0.f, 0.f, 0.f);
    if (BIAS_RELU) bb = *(const float4*)&bias[c0];
    #pragma unroll
    for (int r = 0; r < 8; r++) {
        float4 o;
        o.x = acc[r][0] + bb.x;
        o.y = acc[r][1] + bb.y;
        o.z = acc[r][2] + bb.z;
        o.w = acc[r][3] + bb.w;
        if (BIAS_RELU) {
            o.x = fmaxf(o.x, 0.f); o.y = fmaxf(o.y, 0.f);
            o.z = fmaxf(o.z, 0.f); o.w = fmaxf(o.w, 0.f);
        }
        *(float4*)&Y[(row0 + r0 + r) * NC + c0] = o;
    }
}

// ---------------- FC + softmax (fuses layer-2 bias + relu) ----------------
__global__ void fc_softmax(const float* __restrict__ H, const float* __restrict__ Wfc,
                           const float* __restrict__ bfc, const float* __restrict__ b2,
                           float* __restrict__ out) {
    int g = blockIdx.x;
    int tid = threadIdx.x;      // 256
    const float* hrow = H + g * 8192;

    float a0 = 0.f, a1 = 0.f, a2 = 0.f, a3 = 0.f;
    for (int j = tid; j < 8192; j += 256) {
        float v = hrow[j] + b2[j & 63];
        v = fmaxf(v, 0.f);
        float4 w = __ldg((const float4*)Wfc + j);
        a0 = fmaf(v, w.x, a0);
        a1 = fmaf(v, w.y, a1);
        a2 = fmaf(v, w.z, a2);
        a3 = fmaf(v, w.w, a3);
    }
    #pragma unroll
    for (int off = 16; off > 0; off >>= 1) {
        a0 += __shfl_xor_sync(0xffffffffu, a0, off);
        a1 += __shfl_xor_sync(0xffffffffu, a1, off);
        a2 += __shfl_xor_sync(0xffffffffu, a2, off);
        a3 += __shfl_xor_sync(0xffffffffu, a3, off);
    }
    __shared__ float sred[8][4];
    int lane = tid & 31, warp = tid >> 5;
    if (lane == 0) {
        sred[warp][0] = a0; sred[warp][1] = a1;
        sred[warp][2] = a2; sred[warp][3] = a3;
    }
    __syncthreads();
    if (tid == 0) {
        float l[4];
        #pragma unroll
        for (int c = 0; c < 4; c++) {
            float s = bfc[c];
            #pragma unroll
            for (int w = 0; w < 8; w++) s += sred[w][c];
            l[c] = s;
        }
        float m = fmaxf(fmaxf(l[0], l[1]), fmaxf(l[2], l[3]));
        float e0 = __expf(l[0] - m), e1 = __expf(l[1] - m);
        float e2 = __expf(l[2] - m), e3 = __expf(l[3] - m);
        float inv = 1.0f / (e0 + e1 + e2 + e3);
        out[g * 4 + 0] = e0 * inv;
        out[g * 4 + 1] = e1 * inv;
        out[g * 4 + 2] = e2 * inv;
        out[g * 4 + 3] = e3 * inv;
    }
}

// ---------------- launch ----------------
extern "C" void kernel_launch(void* const* d_in, const int* in_sizes, int n_in,
                              void* d_out, int out_size) {
    const float* x   = (const float*)d_in[0];
    const int*   ei  = (const int*)d_in[1];
    const float* ew  = (const float*)d_in[2];
    const float* W1  = (const float*)d_in[3];
    const float* b1  = (const float*)d_in[4];
    const float* W2  = (const float*)d_in[5];
    const float* b2  = (const float*)d_in[6];
    const float* Wfc = (const float*)d_in[7];
    const float* bfc = (const float*)d_in[8];
    float* out = (float*)d_out;

    float* aggx; cudaGetSymbolAddress((void**)&aggx, g_aggx);
    float* h1;   cudaGetSymbolAddress((void**)&h1, g_h1);
    float* h2t;  cudaGetSymbolAddress((void**)&h2t, g_h2t);
    float* h2;   cudaGetSymbolAddress((void**)&h2, g_h2);

    // normalization + CSR build
    k_init<<<NN / 256, 256>>>();
    k_deg_hist<<<EE / 256, 256>>>(ei, ew);
    k_dis<<<NN / 256, 256>>>();
    k_scan1<<<128, 256>>>();
    k_scan2<<<1, 128>>>();
    k_scan3<<<NN / 256, 256>>>();
    k_scatter<<<EE / 256, 256>>>(ei, ew);

    // layer 1: aggregate x (64 feats), then GEMM (64->128) with bias+relu
    k_agg_csr<<<NN / 8, 256>>>(x, aggx);
    gemm_k<64, 128, 64, true><<<NN / 64, 256>>>(aggx, W1, b1, h1);

    // layer 2: GEMM (128->64), then aggregate; bias+relu deferred to FC
    gemm_k<128, 64, 64, false><<<NN / 64, 128>>>(h1, W2, nullptr, h2t);
    k_agg_csr<<<NN / 8, 256>>>(h2t, h2);

    // FC + softmax
    fc_softmax<<<1024, 256>>>(h2, Wfc, bfc, b2, out);
}